// round 15
// baseline (speedup 1.0000x reference)
#include <cuda_runtime.h>
#include <cuda_fp16.h>

#define NN 50000
#define DD 128
#define EE 800000
#define EH 400000    // EE/2
#define NCHUNK 196   // ceil(NN/256)

// ---- scratch (__device__ globals: allocation-free) ----
// Zero-initialized at module load; every call restores/overwrites state:
//   g_cntrow zeroed by k_scan1 after reading; g_degcol zeroed by k_scatter_dis;
//   g_off/g_boff/g_xh fully rewritten each call; g_maxbits never reset (zero
//   decodes below any ford() value; atomicMax w/ identical data replay-idempotent).
__device__ int   g_degcol[NN];     // degree over col (for norm)
__device__ int   g_cntrow[NN];     // degree over row (for CSR)
__device__ int   g_off[NN];        // local prefix (excl -> incl after scatter)
__device__ int   g_scol[EE];       // edges sorted by row: col ids
__device__ float g_dis[NN];        // deg_col^-0.5 (0 if deg==0)
__device__ float g_ldis[NN];       // log2(dis) - M2  (-inf if deg==0)
__device__ uint2 g_xh[NN * 32];    // x as fp16: 4 halves per uint2 (12.8MB)
__device__ int   g_bsum[NCHUNK];   // per-chunk sums (scan phase 1)
__device__ int   g_boff[NCHUNK];   // per-chunk exclusive offsets (phase 2)
__device__ unsigned int g_maxbits; // ordered-float max of x
__device__ float2 g_ppM;           // (pp*log2e, pp*max(x)*log2e) EX2-prefolded

__device__ __forceinline__ unsigned int ford(float f) {
    unsigned int b = __float_as_uint(f);
    return (b & 0x80000000u) ? ~b : (b | 0x80000000u);
}
__device__ __forceinline__ float funord(unsigned int u) {
    unsigned int b = (u & 0x80000000u) ? (u & 0x7FFFFFFFu) : ~u;
    return __uint_as_float(b);
}
__device__ __forceinline__ float ex2(float z) {
    float r;
    asm("ex2.approx.f32 %0, %1;" : "=f"(r) : "f"(z));
    return r;
}
__device__ __forceinline__ float lg2(float z) {
    float r;
    asm("lg2.approx.f32 %0, %1;" : "=f"(r) : "f"(z));
    return r;
}

// L1: edge histograms, 2 independent edges/thread (MLP 2 on atomic chains)
// + rider: x-max AND fp16 conversion of x (stream in atomic dead slots).
__global__ void __launch_bounds__(256) k_count_max(const int* __restrict__ ei,
                                                   const float* __restrict__ x) {
    int t = blockIdx.x * 256 + threadIdx.x;   // grid covers EH=400128 >= 400000
    if (t < EH) {
        int r0 = __ldg(&ei[t]);
        int r1 = __ldg(&ei[EH + t]);
        int c0 = __ldg(&ei[EE + t]);
        int c1 = __ldg(&ei[EE + EH + t]);
        atomicAdd(&g_cntrow[r0], 1);
        atomicAdd(&g_cntrow[r1], 1);
        atomicAdd(&g_degcol[c0], 1);
        atomicAdd(&g_degcol[c1], 1);
    }

    float m = -3.402823466e38f;
    const float4* x4 = (const float4*)x;
    const int n4 = (NN * DD) / 4;
    const int gsz = gridDim.x * 256;
    for (int i = blockIdx.x * 256 + threadIdx.x; i < n4; i += gsz) {
        float4 v = x4[i];
        m = fmaxf(m, fmaxf(fmaxf(v.x, v.y), fmaxf(v.z, v.w)));
        __half2 a = __floats2half2_rn(v.x, v.y);
        __half2 b = __floats2half2_rn(v.z, v.w);
        uint2 u;
        u.x = *reinterpret_cast<const unsigned int*>(&a);
        u.y = *reinterpret_cast<const unsigned int*>(&b);
        g_xh[i] = u;
    }
#pragma unroll
    for (int o = 16; o; o >>= 1) m = fmaxf(m, __shfl_xor_sync(~0u, m, o));
    __shared__ float sm[8];
    int lane = threadIdx.x & 31, w = threadIdx.x >> 5;
    if (lane == 0) sm[w] = m;
    __syncthreads();
    if (w == 0) {
        m = (lane < 8) ? sm[lane] : -3.402823466e38f;
#pragma unroll
        for (int o = 4; o; o >>= 1) m = fmaxf(m, __shfl_xor_sync(~0u, m, o));
        if (lane == 0) atomicMax(&g_maxbits, ford(m));
    }
}

// L2 (scan phase 1, 196 x 256): local exclusive scan of each 256-chunk of
// g_cntrow into g_off; chunk sum into g_bsum; zero g_cntrow behind itself.
__global__ void __launch_bounds__(256) k_scan1() {
    __shared__ int sh[256];
    int tid = threadIdx.x;
    int i = blockIdx.x * 256 + tid;
    int v = 0;
    if (i < NN) {
        v = g_cntrow[i];
        g_cntrow[i] = 0;          // restore zero-invariant
    }
    sh[tid] = v;
    __syncthreads();
#pragma unroll
    for (int off = 1; off < 256; off <<= 1) {
        int t = (tid >= off) ? sh[tid - off] : 0;
        __syncthreads();
        sh[tid] += t;
        __syncthreads();
    }
    if (i < NN) g_off[i] = sh[tid] - v;           // exclusive local prefix
    if (tid == 255) g_bsum[blockIdx.x] = sh[255]; // chunk total
}

// L3 (scan phase 2, 1 x 256): scan the 196 chunk sums; compute ppM.
__global__ void __launch_bounds__(256) k_scan2(const float* __restrict__ p) {
    __shared__ int sh[256];
    int tid = threadIdx.x;
    int v = (tid < NCHUNK) ? g_bsum[tid] : 0;
    sh[tid] = v;
    __syncthreads();
#pragma unroll
    for (int off = 1; off < 256; off <<= 1) {
        int t = (tid >= off) ? sh[tid - off] : 0;
        __syncthreads();
        sh[tid] += t;
        __syncthreads();
    }
    if (tid < NCHUNK) g_boff[tid] = sh[tid] - v;  // exclusive
    if (tid == 0) {
        const float LOG2E = 1.44269504088896340736f;
        float pp = 2.0f / (1.0f + __expf(-p[0]));
        float M = pp * funord(g_maxbits);
        g_ppM = make_float2(pp * LOG2E, M * LOG2E);
    }
}

// L4: scatter cols, 2 independent edges/thread (MLP 2 on atomic chains);
// bumps g_off[r] directly, pos = local + g_boff[chunk].
// Rider: dis/ldis + degcol zeroing for t < NN.
__global__ void __launch_bounds__(256) k_scatter_dis(const int* __restrict__ ei) {
    int t = blockIdx.x * 256 + threadIdx.x;
    if (t < EH) {
        int r0 = __ldg(&ei[t]);
        int r1 = __ldg(&ei[EH + t]);
        int c0 = __ldg(&ei[EE + t]);
        int c1 = __ldg(&ei[EE + EH + t]);
        int p0 = atomicAdd(&g_off[r0], 1);
        int p1 = atomicAdd(&g_off[r1], 1);
        g_scol[p0 + __ldg(&g_boff[r0 >> 8])] = c0;
        g_scol[p1 + __ldg(&g_boff[r1 >> 8])] = c1;
    }
    if (t < NN) {
        int dg = g_degcol[t];
        g_degcol[t] = 0;          // restore zero-invariant
        float M2 = g_ppM.y;
        if (dg > 0) {
            float dis = rsqrtf((float)dg);
            g_dis[t]  = dis;
            g_ldis[t] = lg2(dis) - M2;
        } else {
            g_dis[t]  = 0.0f;
            g_ldis[t] = -__int_as_float(0x7f800000); // -inf -> ex2() == 0
        }
    }
}

// L5: 64-thread block = 2 independent warps, each warp handles one node.
// Lane l owns features 4l..4l+3, gathered as fp16 (LDG.64 -> 2 sectors/edge).
__global__ void __launch_bounds__(64) k_main(const float* __restrict__ x,
                                             const float* __restrict__ eps,
                                             float* __restrict__ out) {
    const int w    = threadIdx.x >> 5;
    const int lane = threadIdx.x & 31;
    const int r    = blockIdx.x * 2 + w;   // grid = NN/2 exactly
    const int end   = __ldg(&g_off[r]) + __ldg(&g_boff[r >> 8]);
    const int start = (r == 0) ? 0
                    : __ldg(&g_off[r - 1]) + __ldg(&g_boff[(r - 1) >> 8]);
    const float pp2 = g_ppM.x;
    const float4* __restrict__ x4 = (const float4*)x;

    __shared__ int   s_c[64];
    __shared__ float s_w[64];
    int*   sc = s_c + w * 32;
    float* sw = s_w + w * 32;

    float4 num = make_float4(0.f, 0.f, 0.f, 0.f);
    float4 den = make_float4(0.f, 0.f, 0.f, 0.f);

#define EDGE(u, lw)                                                   \
    {                                                                 \
        float2 f01 = __half22float2(*reinterpret_cast<__half2*>(&(u).x)); \
        float2 f23 = __half22float2(*reinterpret_cast<__half2*>(&(u).y)); \
        float ax = ex2(fmaf(pp2, f01.x, (lw)));                       \
        float ay = ex2(fmaf(pp2, f01.y, (lw)));                       \
        float az = ex2(fmaf(pp2, f23.x, (lw)));                       \
        float aw = ex2(fmaf(pp2, f23.y, (lw)));                       \
        den.x += ax; num.x = fmaf(ax, f01.x, num.x);                  \
        den.y += ay; num.y = fmaf(ay, f01.y, num.y);                  \
        den.z += az; num.z = fmaf(az, f23.x, num.z);                  \
        den.w += aw; num.w = fmaf(aw, f23.y, num.w);                  \
    }

    for (int base = start; base < end; base += 32) {
        int j = base + lane;
        if (j < end) {
            int c = g_scol[j];
            sc[lane] = c;
            sw[lane] = g_ldis[c];
        }
        __syncwarp();
        int m = end - base;
        if (m > 32) m = 32;
        int k = 0;
        for (; k + 4 <= m; k += 4) {
            int   c0 = sc[k],     c1 = sc[k + 1], c2 = sc[k + 2], c3 = sc[k + 3];
            float w0 = sw[k],     w1 = sw[k + 1], w2 = sw[k + 2], w3 = sw[k + 3];
            uint2 u0 = __ldg(&g_xh[c0 * 32 + lane]);
            uint2 u1 = __ldg(&g_xh[c1 * 32 + lane]);
            uint2 u2 = __ldg(&g_xh[c2 * 32 + lane]);
            uint2 u3 = __ldg(&g_xh[c3 * 32 + lane]);
            EDGE(u0, w0) EDGE(u1, w1) EDGE(u2, w2) EDGE(u3, w3)
        }
        for (; k < m; k++) {
            int   c = sc[k];
            float lw = sw[k];
            uint2 u = __ldg(&g_xh[c * 32 + lane]);
            EDGE(u, lw)
        }
        __syncwarp();
    }
#undef EDGE

    float dr = g_dis[r];
    float e1 = 1.0f + eps[0];
    float4 xv = __ldg(&x4[r * 32 + lane]);   // fp32: exact residual term
    float4 o;
    o.x = __fdividef(dr * num.x, fmaf(dr, den.x, 1e-6f)) + e1 * xv.x;
    o.y = __fdividef(dr * num.y, fmaf(dr, den.y, 1e-6f)) + e1 * xv.y;
    o.z = __fdividef(dr * num.z, fmaf(dr, den.z, 1e-6f)) + e1 * xv.z;
    o.w = __fdividef(dr * num.w, fmaf(dr, den.w, 1e-6f)) + e1 * xv.w;
    ((float4*)out)[r * 32 + lane] = o;
}

extern "C" void kernel_launch(void* const* d_in, const int* in_sizes, int n_in,
                              void* d_out, int out_size) {
    const float* x   = (const float*)d_in[0];
    const int*   ei  = (const int*)d_in[1];
    const float* eps = (const float*)d_in[2];
    const float* p   = (const float*)d_in[3];
    float* out = (float*)d_out;

    const int gEH = (EH + 255) / 256;   // 1563 blocks cover 400128 threads

    k_count_max  <<<gEH, 256>>>(ei, x);
    k_scan1      <<<NCHUNK, 256>>>();
    k_scan2      <<<1, 256>>>(p);
    k_scatter_dis<<<gEH, 256>>>(ei);
    k_main       <<<NN / 2, 64>>>(x, eps, out);
}

// round 17
// speedup vs baseline: 1.0450x; 1.0450x over previous
#include <cuda_runtime.h>
#include <cuda_fp16.h>

#define NN 50000
#define DD 128
#define EE 800000
#define NCHUNK 196   // ceil(NN/256)
static_assert(NCHUNK <= 256, "final-block scan must fit one 256-thread block");

// ---- scratch (__device__ globals: allocation-free) ----
// Zero-initialized at module load; every call restores/overwrites state:
//   g_cntrow zeroed by k_scan_p after reading; g_degcol zeroed by k_scatter_dis;
//   g_done reset by the last scan block; g_off/g_boff/g_xh rewritten each call;
//   g_maxbits never reset (zero decodes below any ford() value; atomicMax with
//   identical data is replay-idempotent).
__device__ int   g_degcol[NN];     // degree over col (for norm)
__device__ int   g_cntrow[NN];     // degree over row (for CSR)
__device__ int   g_off[NN];        // local prefix (excl -> incl after scatter)
__device__ int   g_scol[EE];       // edges sorted by row: col ids
__device__ float g_dis[NN];        // deg_col^-0.5 (0 if deg==0)
__device__ float g_ldis[NN];       // log2(dis) - M2  (-inf if deg==0)
__device__ uint2 g_xh[NN * 32];    // x as fp16: 4 halves per uint2 (12.8MB)
__device__ int   g_bsum[NCHUNK];   // per-chunk sums
__device__ int   g_boff[NCHUNK];   // per-chunk exclusive offsets
__device__ unsigned int g_done;    // last-block-done ticket (self-resetting)
__device__ unsigned int g_maxbits; // ordered-float max of x
__device__ float2 g_ppM;           // (pp*log2e, pp*max(x)*log2e) EX2-prefolded

__device__ __forceinline__ unsigned int ford(float f) {
    unsigned int b = __float_as_uint(f);
    return (b & 0x80000000u) ? ~b : (b | 0x80000000u);
}
__device__ __forceinline__ float funord(unsigned int u) {
    unsigned int b = (u & 0x80000000u) ? (u & 0x7FFFFFFFu) : ~u;
    return __uint_as_float(b);
}
__device__ __forceinline__ float ex2(float z) {
    float r;
    asm("ex2.approx.f32 %0, %1;" : "=f"(r) : "f"(z));
    return r;
}
__device__ __forceinline__ float lg2(float z) {
    float r;
    asm("lg2.approx.f32 %0, %1;" : "=f"(r) : "f"(z));
    return r;
}

// L1: edge histograms (1 edge/thread; throughput-bound) + rider:
// x-max AND fp16 conversion of x in the atomic dead slots. EE == 3125*256.
__global__ void __launch_bounds__(256) k_count_max(const int* __restrict__ ei,
                                                   const float* __restrict__ x) {
    int e = blockIdx.x * 256 + threadIdx.x;
    atomicAdd(&g_cntrow[__ldg(&ei[e])], 1);
    atomicAdd(&g_degcol[__ldg(&ei[EE + e])], 1);

    float m = -3.402823466e38f;
    const float4* x4 = (const float4*)x;
    const int n4 = (NN * DD) / 4;
    const int gsz = gridDim.x * 256;
    for (int i = e; i < n4; i += gsz) {
        float4 v = x4[i];
        m = fmaxf(m, fmaxf(fmaxf(v.x, v.y), fmaxf(v.z, v.w)));
        __half2 a = __floats2half2_rn(v.x, v.y);
        __half2 b = __floats2half2_rn(v.z, v.w);
        uint2 u;
        u.x = *reinterpret_cast<const unsigned int*>(&a);
        u.y = *reinterpret_cast<const unsigned int*>(&b);
        g_xh[i] = u;
    }
#pragma unroll
    for (int o = 16; o; o >>= 1) m = fmaxf(m, __shfl_xor_sync(~0u, m, o));
    __shared__ float sm[8];
    int lane = threadIdx.x & 31, w = threadIdx.x >> 5;
    if (lane == 0) sm[w] = m;
    __syncthreads();
    if (w == 0) {
        m = (lane < 8) ? sm[lane] : -3.402823466e38f;
#pragma unroll
        for (int o = 4; o; o >>= 1) m = fmaxf(m, __shfl_xor_sync(~0u, m, o));
        if (lane == 0) atomicMax(&g_maxbits, ford(m));
    }
}

// L2 (merged scan, 196 x 256): each block locally scans its 256-chunk of
// g_cntrow into g_off (zeroing g_cntrow); the LAST block to finish scans the
// 196 chunk sums into g_boff, computes ppM, and resets the ticket.
__global__ void __launch_bounds__(256) k_scan_p(const float* __restrict__ p) {
    __shared__ int sh[256];
    __shared__ bool last;
    int tid = threadIdx.x;
    int i = blockIdx.x * 256 + tid;
    int v = 0;
    if (i < NN) {
        v = g_cntrow[i];
        g_cntrow[i] = 0;          // restore zero-invariant
    }
    sh[tid] = v;
    __syncthreads();
#pragma unroll
    for (int off = 1; off < 256; off <<= 1) {
        int t = (tid >= off) ? sh[tid - off] : 0;
        __syncthreads();
        sh[tid] += t;
        __syncthreads();
    }
    if (i < NN) g_off[i] = sh[tid] - v;           // exclusive local prefix
    if (tid == 255) g_bsum[blockIdx.x] = sh[255]; // chunk total

    // last-block-done handshake
    __threadfence();
    if (tid == 0) {
        unsigned int ticket = atomicAdd(&g_done, 1u);
        last = (ticket == NCHUNK - 1);
    }
    __syncthreads();
    if (!last) return;

    // final block: scan the 196 chunk sums (fence-ordered; volatile reads)
    int b = (tid < NCHUNK) ? *((volatile int*)&g_bsum[tid]) : 0;
    int bv = b;
    sh[tid] = b;
    __syncthreads();
#pragma unroll
    for (int off = 1; off < 256; off <<= 1) {
        int t = (tid >= off) ? sh[tid - off] : 0;
        __syncthreads();
        sh[tid] += t;
        __syncthreads();
    }
    if (tid < NCHUNK) g_boff[tid] = sh[tid] - bv; // exclusive
    if (tid == 0) {
        g_done = 0;               // reset ticket for next replay
        const float LOG2E = 1.44269504088896340736f;
        float pp = 2.0f / (1.0f + __expf(-p[0]));
        float M = pp * funord(g_maxbits);
        g_ppM = make_float2(pp * LOG2E, M * LOG2E);
    }
}

// L3: scatter cols (1 edge/thread); bumps g_off[r] directly,
// pos = local + g_boff[chunk]. Rider: dis/ldis + degcol zeroing.
__global__ void __launch_bounds__(256) k_scatter_dis(const int* __restrict__ ei) {
    int e = blockIdx.x * 256 + threadIdx.x;
    int r = __ldg(&ei[e]);
    int c = __ldg(&ei[EE + e]);
    int pos = atomicAdd(&g_off[r], 1) + __ldg(&g_boff[r >> 8]);
    g_scol[pos] = c;
    if (e < NN) {
        int dg = g_degcol[e];
        g_degcol[e] = 0;          // restore zero-invariant
        float M2 = g_ppM.y;
        if (dg > 0) {
            float dis = rsqrtf((float)dg);
            g_dis[e]  = dis;
            g_ldis[e] = lg2(dis) - M2;
        } else {
            g_dis[e]  = 0.0f;
            g_ldis[e] = -__int_as_float(0x7f800000); // -inf -> ex2() == 0
        }
    }
}

// L4: 64-thread block = 2 independent warps, each warp handles one node.
// Lane l owns features 4l..4l+3, gathered as fp16 (LDG.64 -> 2 sectors/edge).
__global__ void __launch_bounds__(64) k_main(const float* __restrict__ x,
                                             const float* __restrict__ eps,
                                             float* __restrict__ out) {
    const int w    = threadIdx.x >> 5;
    const int lane = threadIdx.x & 31;
    const int r    = blockIdx.x * 2 + w;   // grid = NN/2 exactly
    const int end   = __ldg(&g_off[r]) + __ldg(&g_boff[r >> 8]);
    const int start = (r == 0) ? 0
                    : __ldg(&g_off[r - 1]) + __ldg(&g_boff[(r - 1) >> 8]);
    const float pp2 = g_ppM.x;
    const float4* __restrict__ x4 = (const float4*)x;

    __shared__ int   s_c[64];
    __shared__ float s_w[64];
    int*   sc = s_c + w * 32;
    float* sw = s_w + w * 32;

    float4 num = make_float4(0.f, 0.f, 0.f, 0.f);
    float4 den = make_float4(0.f, 0.f, 0.f, 0.f);

#define EDGE(u, lw)                                                   \
    {                                                                 \
        float2 f01 = __half22float2(*reinterpret_cast<__half2*>(&(u).x)); \
        float2 f23 = __half22float2(*reinterpret_cast<__half2*>(&(u).y)); \
        float ax = ex2(fmaf(pp2, f01.x, (lw)));                       \
        float ay = ex2(fmaf(pp2, f01.y, (lw)));                       \
        float az = ex2(fmaf(pp2, f23.x, (lw)));                       \
        float aw = ex2(fmaf(pp2, f23.y, (lw)));                       \
        den.x += ax; num.x = fmaf(ax, f01.x, num.x);                  \
        den.y += ay; num.y = fmaf(ay, f01.y, num.y);                  \
        den.z += az; num.z = fmaf(az, f23.x, num.z);                  \
        den.w += aw; num.w = fmaf(aw, f23.y, num.w);                  \
    }

    for (int base = start; base < end; base += 32) {
        int j = base + lane;
        if (j < end) {
            int c = g_scol[j];
            sc[lane] = c;
            sw[lane] = g_ldis[c];
        }
        __syncwarp();
        int m = end - base;
        if (m > 32) m = 32;
        int k = 0;
        for (; k + 4 <= m; k += 4) {
            int   c0 = sc[k],     c1 = sc[k + 1], c2 = sc[k + 2], c3 = sc[k + 3];
            float w0 = sw[k],     w1 = sw[k + 1], w2 = sw[k + 2], w3 = sw[k + 3];
            uint2 u0 = __ldg(&g_xh[c0 * 32 + lane]);
            uint2 u1 = __ldg(&g_xh[c1 * 32 + lane]);
            uint2 u2 = __ldg(&g_xh[c2 * 32 + lane]);
            uint2 u3 = __ldg(&g_xh[c3 * 32 + lane]);
            EDGE(u0, w0) EDGE(u1, w1) EDGE(u2, w2) EDGE(u3, w3)
        }
        for (; k < m; k++) {
            int   c = sc[k];
            float lw = sw[k];
            uint2 u = __ldg(&g_xh[c * 32 + lane]);
            EDGE(u, lw)
        }
        __syncwarp();
    }
#undef EDGE

    float dr = g_dis[r];
    float e1 = 1.0f + eps[0];
    float4 xv = __ldg(&x4[r * 32 + lane]);   // fp32: exact residual term
    float4 o;
    o.x = __fdividef(dr * num.x, fmaf(dr, den.x, 1e-6f)) + e1 * xv.x;
    o.y = __fdividef(dr * num.y, fmaf(dr, den.y, 1e-6f)) + e1 * xv.y;
    o.z = __fdividef(dr * num.z, fmaf(dr, den.z, 1e-6f)) + e1 * xv.z;
    o.w = __fdividef(dr * num.w, fmaf(dr, den.w, 1e-6f)) + e1 * xv.w;
    ((float4*)out)[r * 32 + lane] = o;
}

extern "C" void kernel_launch(void* const* d_in, const int* in_sizes, int n_in,
                              void* d_out, int out_size) {
    const float* x   = (const float*)d_in[0];
    const int*   ei  = (const int*)d_in[1];
    const float* eps = (const float*)d_in[2];
    const float* p   = (const float*)d_in[3];
    float* out = (float*)d_out;

    k_count_max  <<<EE / 256, 256>>>(ei, x);
    k_scan_p     <<<NCHUNK, 256>>>(p);
    k_scatter_dis<<<EE / 256, 256>>>(ei);
    k_main       <<<NN / 2, 64>>>(x, eps, out);
}